// round 1
// baseline (speedup 1.0000x reference)
#include <cuda_runtime.h>

#define N_NODES 100000
#define DIM 64
#define EPW 128   // edges per warp in aggregation

// Scratch: aggY[i] = (sum_{edges -> i} X[col]) / dd1[i]
__device__ float g_aggY[(size_t)N_NODES * DIM];

// ---------------------------------------------------------------------------
// Zero the scratch (must be re-zeroed every call: graph replays).
// ---------------------------------------------------------------------------
__global__ void zero_aggY_kernel() {
    int i = blockIdx.x * blockDim.x + threadIdx.x;
    int n4 = (N_NODES * DIM) / 4;
    if (i < n4) {
        ((float4*)g_aggY)[i] = make_float4(0.f, 0.f, 0.f, 0.f);
    }
}

// ---------------------------------------------------------------------------
// Edge aggregation: warp-segmented sum exploiting sorted row_ids.
// Each warp owns EPW consecutive edges; lanes each own 2 of the 64 features.
// Accumulate in registers while the destination row is unchanged; flush with
// atomicAdd (scaled by 1/dd1[row]) on segment change or chunk end.
// ---------------------------------------------------------------------------
__global__ void agg_kernel(const float* __restrict__ X,
                           const int* __restrict__ rows,
                           const int* __restrict__ cols,
                           const float* __restrict__ dd1,
                           int E) {
    int warp = (blockIdx.x * blockDim.x + threadIdx.x) >> 5;
    int lane = threadIdx.x & 31;
    int base = warp * EPW;
    if (base >= E) return;
    int end = min(base + EPW, E);

    float ax = 0.f, ay = 0.f;
    int cur = __ldg(rows + base);

    for (int e0 = base; e0 < end; e0 += 32) {
        int n = min(32, end - e0);
        int r = -1, c = 0;
        if (lane < n) {
            r = __ldg(rows + e0 + lane);
            c = __ldg(cols + e0 + lane);
        }
        for (int i = 0; i < n; i++) {
            int ri = __shfl_sync(0xffffffffu, r, i);
            int ci = __shfl_sync(0xffffffffu, c, i);
            if (ri != cur) {
                float inv = 1.0f / __ldg(dd1 + cur);
                float* dst = g_aggY + (size_t)cur * DIM + 2 * lane;
                atomicAdd(dst + 0, ax * inv);
                atomicAdd(dst + 1, ay * inv);
                ax = 0.f; ay = 0.f;
                cur = ri;
            }
            float2 v = __ldg((const float2*)(X + (size_t)ci * DIM) + lane);
            ax += v.x;
            ay += v.y;
        }
    }
    float inv = 1.0f / __ldg(dd1 + cur);
    float* dst = g_aggY + (size_t)cur * DIM + 2 * lane;
    atomicAdd(dst + 0, ax * inv);
    atomicAdd(dst + 1, ay * inv);
}

// ---------------------------------------------------------------------------
// Fused dual GEMM: out = aggY @ W + X @ W1
// 64 rows per block, 256 threads, 4x4 register tile per thread.
// Shared: Xs/Ys row-major padded [64][65] (pad kills stride-64 conflicts),
// Ws/W1s [64][64]. ~66 KB -> dynamic shared memory.
// ---------------------------------------------------------------------------
__global__ __launch_bounds__(256) void gemm_kernel(const float* __restrict__ X,
                                                   const float* __restrict__ W,
                                                   const float* __restrict__ W1,
                                                   float* __restrict__ out,
                                                   int N) {
    extern __shared__ float smem[];
    float* Xs  = smem;                      // [64][65]
    float* Ys  = Xs + 64 * 65;              // [64][65]
    float* Ws  = Ys + 64 * 65;              // [64][64]
    float* W1s = Ws + 64 * 64;              // [64][64]

    int tid  = threadIdx.x;
    int row0 = blockIdx.x * 64;

    // Load W, W1 (contiguous 4096 floats each)
    for (int i = tid; i < (DIM * DIM) / 4; i += 256) {
        ((float4*)Ws)[i]  = __ldg((const float4*)W + i);
        ((float4*)W1s)[i] = __ldg((const float4*)W1 + i);
    }

    // Load 64-row slabs of X and aggY into shared (row-major, padded 65)
    for (int idx = tid; idx < 64 * 16; idx += 256) {
        int r  = idx >> 4;          // 0..63
        int k4 = (idx & 15) * 4;    // 0,4,...,60
        int row = row0 + r;
        float4 v = make_float4(0.f, 0.f, 0.f, 0.f);
        float4 u = make_float4(0.f, 0.f, 0.f, 0.f);
        if (row < N) {
            v = __ldg((const float4*)(X + (size_t)row * DIM + k4));
            u = __ldg((const float4*)(g_aggY + (size_t)row * DIM + k4));
        }
        float* xr = Xs + r * 65 + k4;
        xr[0] = v.x; xr[1] = v.y; xr[2] = v.z; xr[3] = v.w;
        float* yr = Ys + r * 65 + k4;
        yr[0] = u.x; yr[1] = u.y; yr[2] = u.z; yr[3] = u.w;
    }
    __syncthreads();

    int cq = tid & 15;      // column quad
    int rq = tid >> 4;      // row quad
    int c0 = cq * 4;
    int r0 = rq * 4;

    float acc[4][4];
#pragma unroll
    for (int i = 0; i < 4; i++)
#pragma unroll
        for (int j = 0; j < 4; j++) acc[i][j] = 0.f;

#pragma unroll 8
    for (int k = 0; k < DIM; k++) {
        float4 wv  = *(const float4*)(Ws  + k * DIM + c0);
        float4 w1v = *(const float4*)(W1s + k * DIM + c0);
        float xk[4], yk[4];
#pragma unroll
        for (int i = 0; i < 4; i++) {
            xk[i] = Xs[(r0 + i) * 65 + k];
            yk[i] = Ys[(r0 + i) * 65 + k];
        }
#pragma unroll
        for (int i = 0; i < 4; i++) {
            acc[i][0] += yk[i] * wv.x + xk[i] * w1v.x;
            acc[i][1] += yk[i] * wv.y + xk[i] * w1v.y;
            acc[i][2] += yk[i] * wv.z + xk[i] * w1v.z;
            acc[i][3] += yk[i] * wv.w + xk[i] * w1v.w;
        }
    }

#pragma unroll
    for (int i = 0; i < 4; i++) {
        int row = row0 + r0 + i;
        if (row < N) {
            float4 o = make_float4(acc[i][0], acc[i][1], acc[i][2], acc[i][3]);
            *(float4*)(out + (size_t)row * DIM + c0) = o;
        }
    }
}

// ---------------------------------------------------------------------------
extern "C" void kernel_launch(void* const* d_in, const int* in_sizes, int n_in,
                              void* d_out, int out_size) {
    const float* X    = (const float*)d_in[0];   // [N, 64]
    const float* W    = (const float*)d_in[1];   // [64, 64]
    const float* W1   = (const float*)d_in[2];   // [64, 64]
    const float* dd1  = (const float*)d_in[3];   // [N, 1]
    const int*   rows = (const int*)d_in[4];     // [E]
    const int*   cols = (const int*)d_in[5];     // [E]
    float*       out  = (float*)d_out;           // [N, 64]

    int N = in_sizes[0] / DIM;
    int E = in_sizes[4];

    // 1) zero scratch
    {
        int n4 = (N_NODES * DIM) / 4;
        zero_aggY_kernel<<<(n4 + 255) / 256, 256>>>();
    }

    // 2) edge aggregation into g_aggY (scaled by 1/dd1)
    {
        int nwarps  = (E + EPW - 1) / EPW;
        int nblocks = (nwarps + 7) / 8;           // 8 warps / block
        agg_kernel<<<nblocks, 256>>>(X, rows, cols, dd1, E);
    }

    // 3) fused dual GEMM -> out
    {
        int nblocks = (N + 63) / 64;
        size_t smem_bytes = (2 * 64 * 65 + 2 * 64 * 64) * sizeof(float);
        cudaFuncSetAttribute(gemm_kernel,
                             cudaFuncAttributeMaxDynamicSharedMemorySize,
                             (int)smem_bytes);
        gemm_kernel<<<nblocks, 256, smem_bytes>>>(X, W, W1, out, N);
    }
}